// round 16
// baseline (speedup 1.0000x reference)
#include <cuda_runtime.h>
#include <stdint.h>

#define B_  32
#define H_  512
#define W_  512
#define PIX_PER_IMG (H_ * W_)                    // 262144
#define CHUNKS 32                                // moments chunks per batch
#define MBLK (B_ * CHUNKS)                       // 1024 hybrid blocks
#define F4_PER_CHUNK (PIX_PER_IMG / CHUNKS / 4)  // 2048 float4 per chunk
#define F4_PER_THREAD (F4_PER_CHUNK / 256)       // 8 (front-batched)
#define SHIFT_ELEMS 8
#define SBLK_PER_B (PIX_PER_IMG / (256 * SHIFT_ELEMS))   // 128
#define GRID_TOTAL (B_ * SBLK_PER_B)             // 4096 blocks total
#define FP_SCALE 1048576.0f                      // 2^20 (exact float scaling)

// Scratch (no allocations allowed) — zero-init; self-reset every launch.
__device__ long long    g_tot[B_ * 3];    // fixed-point (m00,m10,m01) per batch
__device__ int          g_shift[B_ * 2];  // (dx, dy) ints per batch
__device__ unsigned int g_cnt[B_];        // moments arrival counters
__device__ unsigned int g_ready[B_];      // per-batch release flags
__device__ unsigned int g_done;           // global completion counter

// ---------------------------------------------------------------------------
// Single launch, 4096 blocks (exactly the copy-sized grid — no extra slots).
// Blocks 0..1023 (hybrid): moments for batch bid>>5 (butterfly reduce +
//   associative fixed-point atomics; 32nd arrival finalizes (dx,dy) and
//   releases the flag), THEN their own shift slice.
// Blocks 1024..4095: pure shift role.
// Shift role: front-issue ALL x loads at shift-independent addresses
//   (scatter formulation), gate on the batch flag (loads stay in flight),
//   then scatter-store + zero the disjoint border complement.
// Deadlock-free: wave-1 blocks gate only on batches 0..6, whose moments
//   blocks (bids 0..223) are resident and never gate before committing.
// ---------------------------------------------------------------------------
__global__ __launch_bounds__(256, 6)
void fused_kernel(const float4* __restrict__ x,
                  const float*  __restrict__ mk,
                  float4* __restrict__ out)
{
    const int bid  = blockIdx.x;
    const int t    = threadIdx.x;
    const int lane = t & 31;
    const int wid  = t >> 5;

    // =================== Phase A: moments (hybrid blocks only) ===============
    if (bid < MBLK) {
        const int mb    = bid >> 5;          // moments batch 0..31
        const int chunk = bid & (CHUNKS - 1);

        const float4* base =
            (const float4*)(mk + (size_t)mb * PIX_PER_IMG) + chunk * F4_PER_CHUNK;

        float4 v[F4_PER_THREAD];
#pragma unroll
        for (int i = 0; i < F4_PER_THREAD; i++)
            v[i] = base[t + i * 256];

        float s0 = 0.f, s1 = 0.f, s2 = 0.f;
#pragma unroll
        for (int i = 0; i < F4_PER_THREAD; i++) {
            const int p = chunk * (F4_PER_CHUNK * 4) + (t + i * 256) * 4;
            const int h = p >> 9;
            const int w = p & (W_ - 1);
            const float ry  = (float)(h - (H_ / 2));
            const float rx0 = (float)(w - (W_ / 2));
            const float sum = v[i].x + v[i].y + v[i].z + v[i].w;
            s0 += sum;
            s2 += ry * sum;
            s1 += rx0 * v[i].x + (rx0 + 1.f) * v[i].y + (rx0 + 2.f) * v[i].z
                + (rx0 + 3.f) * v[i].w;
        }

#pragma unroll
        for (int m = 16; m > 0; m >>= 1) {
            s0 += __shfl_xor_sync(0xffffffffu, s0, m);
            s1 += __shfl_xor_sync(0xffffffffu, s1, m);
            s2 += __shfl_xor_sync(0xffffffffu, s2, m);
        }

        __shared__ float w0[8], w1[8], w2[8];
        if (lane == 0) { w0[wid] = s0; w1[wid] = s1; w2[wid] = s2; }
        __syncthreads();

        if (t == 0) {
            float r0 = 0.f, r1 = 0.f, r2 = 0.f;
#pragma unroll
            for (int i = 0; i < 8; i++) { r0 += w0[i]; r1 += w1[i]; r2 += w2[i]; }
            atomicAdd((unsigned long long*)&g_tot[mb * 3 + 0],
                      (unsigned long long)llrintf(r0 * FP_SCALE));
            atomicAdd((unsigned long long*)&g_tot[mb * 3 + 1],
                      (unsigned long long)llrintf(r1 * FP_SCALE));
            atomicAdd((unsigned long long*)&g_tot[mb * 3 + 2],
                      (unsigned long long)llrintf(r2 * FP_SCALE));
            __threadfence();

            if (atomicAdd(&g_cnt[mb], 1u) == CHUNKS - 1) {
                const long long t0v = (long long)atomicAdd(
                    (unsigned long long*)&g_tot[mb * 3 + 0], 0ull);
                const long long t1v = (long long)atomicAdd(
                    (unsigned long long*)&g_tot[mb * 3 + 1], 0ull);
                const long long t2v = (long long)atomicAdd(
                    (unsigned long long*)&g_tot[mb * 3 + 2], 0ull);
                const double den = fmax(1048.576, (double)t0v);  // 0.001*2^20
                // rint = round-half-even, matching jnp.round
                g_shift[mb * 2 + 0] = (int)rint((double)t1v / den);   // dx
                g_shift[mb * 2 + 1] = (int)rint((double)t2v / den);   // dy
                g_tot[mb * 3 + 0] = 0ll;
                g_tot[mb * 3 + 1] = 0ll;
                g_tot[mb * 3 + 2] = 0ll;
                g_cnt[mb] = 0u;
                __threadfence();                 // publish g_shift before flag
                atomicExch(&g_ready[mb], 1u);
            }
        }
        __syncthreads();   // w0/w1/w2 smem reuse barrier before shift phase
    }

    // =================== Phase B: shift slice (all blocks) ===================
    {
        const int b     = bid >> 7;               // shift batch
        const int chunk = bid & (SBLK_PER_B - 1);
        const int base  = chunk * (256 * SHIFT_ELEMS);

        const float4* xb = x + ((size_t)b << 18);
        float4* ob       = out + ((size_t)b << 18);

        // Front-issue ALL loads at shift-independent addresses (MLP=8).
        float4 v[SHIFT_ELEMS];
#pragma unroll
        for (int k = 0; k < SHIFT_ELEMS; k++)
            v[k] = xb[base + k * 256 + t];

        // Gate on batch readiness; loads above remain in flight meanwhile.
        __shared__ int s_dx, s_dy;
        if (t == 0) {
            while (atomicAdd(&g_ready[b], 0u) == 0u) __nanosleep(64);
            s_dx = atomicAdd(&((int*)g_shift)[b * 2 + 0], 0);
            s_dy = atomicAdd(&((int*)g_shift)[b * 2 + 1], 0);
        }
        __syncthreads();
        const int dx = s_dx;
        const int dy = s_dy;

#pragma unroll
        for (int k = 0; k < SHIFT_ELEMS; k++) {
            const int p = base + k * 256 + t;    // source pixel (x coords)
            const int h = p >> 9;
            const int w = p & (W_ - 1);
            // Scatter: out[h-dy, w-dx] = x[h, w] when target in bounds.
            const int th = h - dy;
            const int tw = w - dx;
            if ((unsigned)th < (unsigned)H_ && (unsigned)tw < (unsigned)W_)
                ob[(th << 9) + tw] = v[k];
            // Border complement: out[p] = 0 when its source is out of bounds.
            const int sh = h + dy;
            const int sw = w + dx;
            if ((unsigned)sh >= (unsigned)H_ || (unsigned)sw >= (unsigned)W_)
                ob[p] = make_float4(0.f, 0.f, 0.f, 0.f);
        }
    }

    // ---- Replay cleanup: last block overall resets the flags. Every block
    // has passed its gate before incrementing, so no one is stranded.
    __syncthreads();
    if (t == 0) {
        if (atomicAdd(&g_done, 1u) == GRID_TOTAL - 1) {
#pragma unroll
            for (int i = 0; i < B_; i++) g_ready[i] = 0u;
            g_done = 0u;
            __threadfence();
        }
    }
}

// ---------------------------------------------------------------------------
extern "C" void kernel_launch(void* const* d_in, const int* in_sizes, int n_in,
                              void* d_out, int out_size)
{
    const float* x  = (const float*)d_in[0];   // [32,512,512,4]
    const float* mk = (const float*)d_in[1];   // [32,512,512,1]

    fused_kernel<<<GRID_TOTAL, 256>>>((const float4*)x, mk, (float4*)d_out);
}